// round 1
// baseline (speedup 1.0000x reference)
#include <cuda_runtime.h>

#define T_STEPS 20
#define HW (480*480)          // 230400 per (b,t) slab, /4 = 57600 float4
#define NPB 64                // blocks per timestep
#define TPB 256
#define NACC 26
// acc layout: 0:cnt 1:S1p 2:S1t 3:S2p 4:S2t 5:Spt
//             6..10:ptot  11..15:ttot  16..20:hits  21..25:mae_num

__device__ float g_part[T_STEPS * NPB * NACC];

__constant__ float c_tw[T_STEPS] = {
    0.0075f, 0.02f, 0.03f, 0.04f, 0.05f, 0.06f, 0.07f, 0.08f, 0.09f, 0.1f,
    0.09f,   0.08f, 0.07f, 0.06f, 0.05f, 0.04f, 0.03f, 0.02f, 0.0075f, 0.005f};

__device__ __forceinline__ void accum_one(float pn, float tn, float mk,
                                          float (&acc)[NACC]) {
    const float LOGF = 3.4339871883106655f;   // ln(31)
    float p = __expf(pn * LOGF) - 1.0f;
    float q = __expf(tn * LOGF) - 1.0f;
    p = fmaxf(p, 0.0f);
    q = fmaxf(q, 0.0f);
    bool m  = (mk > 0.5f);
    bool cz = m && !((p < 0.1f) && (q < 0.1f));
    if (cz) {
        acc[0] += 1.0f;
        acc[1] += p;
        acc[2] += q;
        acc[3] = fmaf(p, p, acc[3]);
        acc[4] = fmaf(q, q, acc[4]);
        acc[5] = fmaf(p, q, acc[5]);
    }
    float d = fabsf(p - q);
    const float THR[6] = {0.1f, 1.0f, 2.0f, 5.0f, 8.0f, 3.402823466e38f};
#pragma unroll
    for (int l = 0; l < 5; l++) {
        bool pi = m && (p >= THR[l]) && (p < THR[l + 1]);
        bool ti = m && (q >= THR[l]) && (q < THR[l + 1]);
        if (pi)       acc[6 + l]  += 1.0f;
        if (ti)       { acc[11 + l] += 1.0f; acc[21 + l] += d; }
        if (pi && ti) acc[16 + l] += 1.0f;
    }
}

__global__ __launch_bounds__(TPB) void k_accum(const float* __restrict__ pred,
                                               const float* __restrict__ targ,
                                               const float* __restrict__ mask) {
    const int t   = blockIdx.y;
    const int gid = blockIdx.x * TPB + threadIdx.x;   // 0..NPB*TPB-1

    float acc[NACC];
#pragma unroll
    for (int i = 0; i < NACC; i++) acc[i] = 0.0f;

#pragma unroll
    for (int b = 0; b < 2; b++) {
        size_t base = ((size_t)b * T_STEPS + t) * (size_t)HW;
        const float4* p4 = (const float4*)(pred + base);
        const float4* t4 = (const float4*)(targ + base);
        const float4* m4 = (const float4*)(mask + base);
        for (int v = gid; v < HW / 4; v += NPB * TPB) {
            float4 pv = p4[v];
            float4 tv = t4[v];
            float4 mv = m4[v];
            accum_one(pv.x, tv.x, mv.x, acc);
            accum_one(pv.y, tv.y, mv.y, acc);
            accum_one(pv.z, tv.z, mv.z, acc);
            accum_one(pv.w, tv.w, mv.w, acc);
        }
    }

    // warp tree reduce (deterministic)
#pragma unroll
    for (int i = 0; i < NACC; i++) {
#pragma unroll
        for (int o = 16; o > 0; o >>= 1)
            acc[i] += __shfl_xor_sync(0xffffffffu, acc[i], o);
    }

    __shared__ float s[TPB / 32][NACC];
    int w = threadIdx.x >> 5, ln = threadIdx.x & 31;
    if (ln == 0) {
#pragma unroll
        for (int i = 0; i < NACC; i++) s[w][i] = acc[i];
    }
    __syncthreads();
    if (threadIdx.x < NACC) {
        float v = 0.0f;
#pragma unroll
        for (int w2 = 0; w2 < TPB / 32; w2++) v += s[w2][threadIdx.x];
        g_part[((size_t)t * NPB + blockIdx.x) * NACC + threadIdx.x] = v;
    }
}

__global__ void k_reduce(float* __restrict__ out) {
    const int t = blockIdx.x;
    __shared__ double s[NACC];
    int j = threadIdx.x;
    if (j < NACC) {
        double v = 0.0;
        for (int k = 0; k < NPB; k++)
            v += (double)g_part[((size_t)t * NPB + k) * NACC + j];
        s[j] = v;
    }
    __syncthreads();
    if (j == 0) {
        double C = s[0], S1p = s[1], S1t = s[2];
        double S2p = s[3], S2t = s[4], Spt = s[5];
        double r = 0.0;
        if (C > 0.0) {
            double num  = Spt - S1p * S1t / C;
            double varp = S2p - S1p * S1p / C;
            double vart = S2t - S1t * S1t / C;
            if (varp < 0.0) varp = 0.0;
            if (vart < 0.0) vart = 0.0;
            double den = sqrt(varp * vart);
            r = num / (den + 1e-6);
            r = fmin(1.0, fmax(-1.0, r));
        }
        double term_corr = sqrt(exp(r - 1.0));
        const double lw[5] = {0.1, 0.1, 0.2, 0.25, 0.35};
        double sc = 0.0;
#pragma unroll
        for (int l = 0; l < 5; l++) {
            double ptot = s[6 + l], ttot = s[11 + l];
            double hits = s[16 + l], maen = s[21 + l];
            double ts  = hits / (ptot + ttot - hits + 1e-8);
            double mae = (ttot > 0.0) ? (maen / fmax(ttot, 1.0)) : 0.0;
            double tm  = sqrt(exp(-mae / 100.0));
            sc += lw[l] * ts * tm;
            out[41  + t * 5 + l] = (float)ts;
            out[141 + t * 5 + l] = (float)mae;
        }
        out[1 + t]  = (float)(term_corr * sc);
        out[21 + t] = (float)r;
    }
}

__global__ void k_final(float* __restrict__ out) {
    int l = threadIdx.x;
    if (l < 5) {
        float ts = 0.0f, ma = 0.0f;
#pragma unroll
        for (int t = 0; t < T_STEPS; t++) {
            ts += out[41 + t * 5 + l];
            ma += out[141 + t * 5 + l];
        }
        out[241 + l] = ts / (float)T_STEPS;
        out[246 + l] = ma / (float)T_STEPS;
    }
    if (l == 5) {
        float tot = 0.0f;
#pragma unroll
        for (int t = 0; t < T_STEPS; t++) tot += out[1 + t] * c_tw[t];
        out[0] = tot;
    }
}

extern "C" void kernel_launch(void* const* d_in, const int* in_sizes, int n_in,
                              void* d_out, int out_size) {
    const float* pred = (const float*)d_in[0];
    const float* targ = (const float*)d_in[1];
    const float* mask = (const float*)d_in[2];
    float* out = (float*)d_out;

    dim3 g1(NPB, T_STEPS);
    k_accum<<<g1, TPB>>>(pred, targ, mask);
    k_reduce<<<T_STEPS, 32>>>(out);
    k_final<<<1, 32>>>(out);
}

// round 2
// speedup vs baseline: 1.0858x; 1.0858x over previous
#include <cuda_runtime.h>

#define T_STEPS 20
#define HW (480*480)           // 230400 per (b,t) slab; /4 = 57600 float4
#define NPB 64                 // blocks per timestep
#define TPB 256
#define NACC 26
// partial layout: 0:cnt 1:S1p 2:S1t 3:S2p 4:S2t 5:Spt
//                 6..10:ptot 11..15:ttot 16..20:hits 21..25:mae_num

__device__ float        g_part[T_STEPS * NPB * NACC];
__device__ unsigned int g_ticket;   // zero-initialized; self-resets each call

__constant__ float c_tw[T_STEPS] = {
    0.0075f, 0.02f, 0.03f, 0.04f, 0.05f, 0.06f, 0.07f, 0.08f, 0.09f, 0.1f,
    0.09f,   0.08f, 0.07f, 0.06f, 0.05f, 0.04f, 0.03f, 0.02f, 0.0075f, 0.005f};

struct Acc {
    float s1p, s1t, s2p, s2t, spt;
    float mae0, mae1, mae2, mae3, mae4;
    int cnt;
    unsigned ptot, ttot, hits;   // 5 x 6-bit packed fields
};

__device__ __forceinline__ void accum_one(float pn, float tn, float mk, Acc& a) {
    const float K = 4.954196310386875f;   // log2(31)
    float p, q;
    asm("ex2.approx.f32 %0, %1;" : "=f"(p) : "f"(pn * K));
    asm("ex2.approx.f32 %0, %1;" : "=f"(q) : "f"(tn * K));
    p -= 1.0f;                            // inputs in [0,1) -> p,q >= 0
    q -= 1.0f;

    int cp = (p >= 0.1f) + (p >= 1.0f) + (p >= 2.0f) + (p >= 5.0f) + (p >= 8.0f);
    int ct = (q >= 0.1f) + (q >= 1.0f) + (q >= 2.0f) + (q >= 5.0f) + (q >= 8.0f);
    bool m = (mk > 0.5f);
    if (!m) { cp = 0; ct = 0; }

    if (cp + ct >= 1) {                   // masked & not double-zero
        a.cnt += 1;
        a.s1p += p;  a.s1t += q;
        a.s2p = fmaf(p, p, a.s2p);
        a.s2t = fmaf(q, q, a.s2t);
        a.spt = fmaf(p, q, a.spt);
    }

    unsigned ohp = (1u << (6 * cp)) >> 6; // 0 if cp==0, else 1<<(6*(cp-1))
    unsigned oht = (1u << (6 * ct)) >> 6;
    a.ptot += ohp;
    a.ttot += oht;
    if (cp == ct) a.hits += ohp;          // cp==ct==0 adds 0: no extra check

    float d = fabsf(p - q);
    if (ct == 1) a.mae0 += d;
    if (ct == 2) a.mae1 += d;
    if (ct == 3) a.mae2 += d;
    if (ct == 4) a.mae3 += d;
    if (ct == 5) a.mae4 += d;
}

__global__ __launch_bounds__(TPB) void k_fused(const float* __restrict__ pred,
                                               const float* __restrict__ targ,
                                               const float* __restrict__ mask,
                                               float* __restrict__ out) {
    const int t   = blockIdx.y;
    const int gid = blockIdx.x * TPB + threadIdx.x;

    Acc a;
    a.s1p = a.s1t = a.s2p = a.s2t = a.spt = 0.0f;
    a.mae0 = a.mae1 = a.mae2 = a.mae3 = a.mae4 = 0.0f;
    a.cnt = 0; a.ptot = a.ttot = a.hits = 0u;

#pragma unroll
    for (int b = 0; b < 2; b++) {
        size_t base = ((size_t)b * T_STEPS + t) * (size_t)HW;
        const float4* p4 = (const float4*)(pred + base);
        const float4* t4 = (const float4*)(targ + base);
        const float4* m4 = (const float4*)(mask + base);
        for (int v = gid; v < HW / 4; v += NPB * TPB) {
            float4 pv = p4[v];
            float4 tv = t4[v];
            float4 mv = m4[v];
            accum_one(pv.x, tv.x, mv.x, a);
            accum_one(pv.y, tv.y, mv.y, a);
            accum_one(pv.z, tv.z, mv.z, a);
            accum_one(pv.w, tv.w, mv.w, a);
        }
    }

    // unpack to 26 floats
    float acc[NACC];
    acc[0] = (float)a.cnt;
    acc[1] = a.s1p; acc[2] = a.s1t; acc[3] = a.s2p; acc[4] = a.s2t; acc[5] = a.spt;
#pragma unroll
    for (int l = 0; l < 5; l++) {
        acc[6  + l] = (float)((a.ptot >> (6 * l)) & 63u);
        acc[11 + l] = (float)((a.ttot >> (6 * l)) & 63u);
        acc[16 + l] = (float)((a.hits >> (6 * l)) & 63u);
    }
    acc[21] = a.mae0; acc[22] = a.mae1; acc[23] = a.mae2; acc[24] = a.mae3; acc[25] = a.mae4;

    // warp tree reduce (deterministic)
#pragma unroll
    for (int i = 0; i < NACC; i++) {
#pragma unroll
        for (int o = 16; o > 0; o >>= 1)
            acc[i] += __shfl_xor_sync(0xffffffffu, acc[i], o);
    }

    __shared__ float s[TPB / 32][NACC];
    int w = threadIdx.x >> 5, ln = threadIdx.x & 31;
    if (ln == 0) {
#pragma unroll
        for (int i = 0; i < NACC; i++) s[w][i] = acc[i];
    }
    __syncthreads();
    if (threadIdx.x < NACC) {
        float v = 0.0f;
#pragma unroll
        for (int w2 = 0; w2 < TPB / 32; w2++) v += s[w2][threadIdx.x];
        g_part[((size_t)t * NPB + blockIdx.x) * NACC + threadIdx.x] = v;
    }

    // ---- last-block-does-the-rest (deterministic: reads fixed g_part) ----
    __threadfence();
    __syncthreads();
    __shared__ bool amLast;
    if (threadIdx.x == 0) {
        unsigned done = atomicAdd(&g_ticket, 1u);
        amLast = (done == (unsigned)(NPB * T_STEPS - 1));
    }
    __syncthreads();
    if (!amLast) return;
    __threadfence();

    __shared__ double sd[T_STEPS][NACC];
    for (int idx = threadIdx.x; idx < T_STEPS * NACC; idx += TPB) {
        int tt = idx / NACC, j = idx % NACC;
        double v = 0.0;
#pragma unroll 8
        for (int k = 0; k < NPB; k++)
            v += (double)g_part[((size_t)tt * NPB + k) * NACC + j];
        sd[tt][j] = v;
    }
    __syncthreads();

    __shared__ float sts[T_STEPS][5], sma[T_STEPS][5], ssc[T_STEPS];
    if (threadIdx.x < T_STEPS) {
        int tt = threadIdx.x;
        double C = sd[tt][0], S1p = sd[tt][1], S1t = sd[tt][2];
        double S2p = sd[tt][3], S2t = sd[tt][4], Spt = sd[tt][5];
        double r = 0.0;
        if (C > 0.0) {
            double num  = Spt - S1p * S1t / C;
            double varp = S2p - S1p * S1p / C;
            double vart = S2t - S1t * S1t / C;
            if (varp < 0.0) varp = 0.0;
            if (vart < 0.0) vart = 0.0;
            r = num / (sqrt(varp * vart) + 1e-6);
            r = fmin(1.0, fmax(-1.0, r));
        }
        double term_corr = sqrt(exp(r - 1.0));
        const double lw[5] = {0.1, 0.1, 0.2, 0.25, 0.35};
        double sc = 0.0;
#pragma unroll
        for (int l = 0; l < 5; l++) {
            double ptot = sd[tt][6 + l], ttot = sd[tt][11 + l];
            double hits = sd[tt][16 + l], maen = sd[tt][21 + l];
            double ts  = hits / (ptot + ttot - hits + 1e-8);
            double mae = (ttot > 0.0) ? (maen / fmax(ttot, 1.0)) : 0.0;
            sc += lw[l] * ts * sqrt(exp(-mae / 100.0));
            sts[tt][l] = (float)ts;
            sma[tt][l] = (float)mae;
            out[41  + tt * 5 + l] = (float)ts;
            out[141 + tt * 5 + l] = (float)mae;
        }
        float sct = (float)(term_corr * sc);
        ssc[tt] = sct;
        out[1 + tt]  = sct;
        out[21 + tt] = (float)r;
    }
    __syncthreads();

    if (threadIdx.x < 5) {
        int l = threadIdx.x;
        float ts = 0.0f, ma = 0.0f;
#pragma unroll
        for (int tt = 0; tt < T_STEPS; tt++) { ts += sts[tt][l]; ma += sma[tt][l]; }
        out[241 + l] = ts / (float)T_STEPS;
        out[246 + l] = ma / (float)T_STEPS;
    }
    if (threadIdx.x == 5) {
        float tot = 0.0f;
#pragma unroll
        for (int tt = 0; tt < T_STEPS; tt++) tot += ssc[tt] * c_tw[tt];
        out[0] = tot;
    }
    if (threadIdx.x == 0) g_ticket = 0u;   // reset for next graph replay
}

extern "C" void kernel_launch(void* const* d_in, const int* in_sizes, int n_in,
                              void* d_out, int out_size) {
    const float* pred = (const float*)d_in[0];
    const float* targ = (const float*)d_in[1];
    const float* mask = (const float*)d_in[2];
    float* out = (float*)d_out;

    dim3 g1(NPB, T_STEPS);
    k_fused<<<g1, TPB>>>(pred, targ, mask, out);
}

// round 3
// speedup vs baseline: 1.3502x; 1.2435x over previous
#include <cuda_runtime.h>

#define T_STEPS 20
#define HW (480*480)           // 230400 per (b,t) slab; /4 = 57600 float4
#define NPB 64                 // blocks per timestep
#define TPB 256
#define NACC 26
// partial layout: 0:cnt 1:S1p 2:S1t 3:S2p 4:S2t 5:Spt
//                 6..10:ptot 11..15:ttot 16..20:hits 21..25:mae_num

__device__ float        g_part[T_STEPS * NPB * NACC];
__device__ unsigned int g_ticket;   // zero-init; self-resets each call

__constant__ float c_tw[T_STEPS] = {
    0.0075f, 0.02f, 0.03f, 0.04f, 0.05f, 0.06f, 0.07f, 0.08f, 0.09f, 0.1f,
    0.09f,   0.08f, 0.07f, 0.06f, 0.05f, 0.04f, 0.03f, 0.02f, 0.0075f, 0.005f};

// thresholds mapped to normalized space: ln(1+thr)/ln(31)
#define C0 0.02775496f
#define C1 0.20184909f
#define C2 0.31992323f
#define C3 0.52177232f
#define C4 0.63984647f

struct Acc {
    float cnt, s1p, s1t, s2p, s2t, spt;
    float mae0, mae1, mae2, mae3, mae4;
    unsigned ptot, ttot, hits;   // 5 x 6-bit packed fields
};

__device__ __forceinline__ void accum_one(float pn, float tn, float mk, Acc& a) {
    const float K = 4.954196310386875f;   // log2(31)
    float p, q;
    asm("ex2.approx.f32 %0, %1;" : "=f"(p) : "f"(pn * K));
    asm("ex2.approx.f32 %0, %1;" : "=f"(q) : "f"(tn * K));
    p -= 1.0f;                            // inputs in [0,1) -> p,q >= 0
    q -= 1.0f;

    bool m = (mk > 0.5f);
    // bin index from normalized values (monotone map), branchless
    int cp = (int)(pn >= C0) + (int)(pn >= C1) + (int)(pn >= C2)
           + (int)(pn >= C3) + (int)(pn >= C4);
    int ct = (int)(tn >= C0) + (int)(tn >= C1) + (int)(tn >= C2)
           + (int)(tn >= C3) + (int)(tn >= C4);
    cp = m ? cp : 0;
    ct = m ? ct : 0;

    // masked & not double-zero: accumulate raw moments (branchless)
    bool nz = ((cp | ct) != 0);
    float pm = nz ? p : 0.0f;
    float qm = nz ? q : 0.0f;
    a.cnt += nz ? 1.0f : 0.0f;
    a.s1p += pm;
    a.s1t += qm;
    a.s2p = fmaf(pm, p, a.s2p);
    a.s2t = fmaf(qm, q, a.s2t);
    a.spt = fmaf(pm, q, a.spt);

    // packed one-hot histogram (6-bit fields, <=28 elems/thread: no overflow)
    unsigned ohp = (1u << (6 * cp)) >> 6; // 0 if cp==0
    unsigned oht = (1u << (6 * ct)) >> 6;
    a.ptot += ohp;
    a.ttot += oht;
    a.hits += (cp == ct) ? ohp : 0u;

    float d = fabsf(p - q);
    a.mae0 += (ct == 1) ? d : 0.0f;
    a.mae1 += (ct == 2) ? d : 0.0f;
    a.mae2 += (ct == 3) ? d : 0.0f;
    a.mae3 += (ct == 4) ? d : 0.0f;
    a.mae4 += (ct == 5) ? d : 0.0f;
}

__global__ __launch_bounds__(TPB) void k_fused(const float* __restrict__ pred,
                                               const float* __restrict__ targ,
                                               const float* __restrict__ mask,
                                               float* __restrict__ out) {
    const int t   = blockIdx.y;
    const int gid = blockIdx.x * TPB + threadIdx.x;

    Acc a;
    a.cnt = a.s1p = a.s1t = a.s2p = a.s2t = a.spt = 0.0f;
    a.mae0 = a.mae1 = a.mae2 = a.mae3 = a.mae4 = 0.0f;
    a.ptot = a.ttot = a.hits = 0u;

#pragma unroll
    for (int b = 0; b < 2; b++) {
        size_t base = ((size_t)b * T_STEPS + t) * (size_t)HW;
        const float4* p4 = (const float4*)(pred + base);
        const float4* t4 = (const float4*)(targ + base);
        const float4* m4 = (const float4*)(mask + base);
#pragma unroll 2
        for (int v = gid; v < HW / 4; v += NPB * TPB) {
            float4 pv = p4[v];
            float4 tv = t4[v];
            float4 mv = m4[v];
            accum_one(pv.x, tv.x, mv.x, a);
            accum_one(pv.y, tv.y, mv.y, a);
            accum_one(pv.z, tv.z, mv.z, a);
            accum_one(pv.w, tv.w, mv.w, a);
        }
    }

    // unpack to 26 floats
    float acc[NACC];
    acc[0] = a.cnt;
    acc[1] = a.s1p; acc[2] = a.s1t; acc[3] = a.s2p; acc[4] = a.s2t; acc[5] = a.spt;
#pragma unroll
    for (int l = 0; l < 5; l++) {
        acc[6  + l] = (float)((a.ptot >> (6 * l)) & 63u);
        acc[11 + l] = (float)((a.ttot >> (6 * l)) & 63u);
        acc[16 + l] = (float)((a.hits >> (6 * l)) & 63u);
    }
    acc[21] = a.mae0; acc[22] = a.mae1; acc[23] = a.mae2; acc[24] = a.mae3; acc[25] = a.mae4;

    // warp tree reduce (deterministic)
#pragma unroll
    for (int i = 0; i < NACC; i++) {
#pragma unroll
        for (int o = 16; o > 0; o >>= 1)
            acc[i] += __shfl_xor_sync(0xffffffffu, acc[i], o);
    }

    __shared__ float s[TPB / 32][NACC];
    int w = threadIdx.x >> 5, ln = threadIdx.x & 31;
    if (ln == 0) {
#pragma unroll
        for (int i = 0; i < NACC; i++) s[w][i] = acc[i];
    }
    __syncthreads();
    if (threadIdx.x < NACC) {
        float v = 0.0f;
#pragma unroll
        for (int w2 = 0; w2 < TPB / 32; w2++) v += s[w2][threadIdx.x];
        g_part[((size_t)t * NPB + blockIdx.x) * NACC + threadIdx.x] = v;
    }

    // ---- last-block-does-the-rest (deterministic: reads fixed g_part) ----
    __threadfence();
    __syncthreads();
    __shared__ bool amLast;
    if (threadIdx.x == 0) {
        unsigned done = atomicAdd(&g_ticket, 1u);
        amLast = (done == (unsigned)(NPB * T_STEPS - 1));
    }
    __syncthreads();
    if (!amLast) return;
    __threadfence();

    __shared__ double sd[T_STEPS][NACC];
    for (int idx = threadIdx.x; idx < T_STEPS * NACC; idx += TPB) {
        int tt = idx / NACC, j = idx % NACC;
        double v = 0.0;
#pragma unroll 8
        for (int k = 0; k < NPB; k++)
            v += (double)g_part[((size_t)tt * NPB + k) * NACC + j];
        sd[tt][j] = v;
    }
    __syncthreads();

    __shared__ float sts[T_STEPS][5], sma[T_STEPS][5], ssc[T_STEPS];
    if (threadIdx.x < T_STEPS) {
        int tt = threadIdx.x;
        double C = sd[tt][0], S1p = sd[tt][1], S1t = sd[tt][2];
        double S2p = sd[tt][3], S2t = sd[tt][4], Spt = sd[tt][5];
        double r = 0.0;
        if (C > 0.0) {
            double num  = Spt - S1p * S1t / C;
            double varp = S2p - S1p * S1p / C;
            double vart = S2t - S1t * S1t / C;
            if (varp < 0.0) varp = 0.0;
            if (vart < 0.0) vart = 0.0;
            r = num / (sqrt(varp * vart) + 1e-6);
            r = fmin(1.0, fmax(-1.0, r));
        }
        double term_corr = sqrt(exp(r - 1.0));
        const double lw[5] = {0.1, 0.1, 0.2, 0.25, 0.35};
        double sc = 0.0;
#pragma unroll
        for (int l = 0; l < 5; l++) {
            double ptot = sd[tt][6 + l], ttot = sd[tt][11 + l];
            double hits = sd[tt][16 + l], maen = sd[tt][21 + l];
            double ts  = hits / (ptot + ttot - hits + 1e-8);
            double mae = (ttot > 0.0) ? (maen / fmax(ttot, 1.0)) : 0.0;
            sc += lw[l] * ts * sqrt(exp(-mae / 100.0));
            sts[tt][l] = (float)ts;
            sma[tt][l] = (float)mae;
            out[41  + tt * 5 + l] = (float)ts;
            out[141 + tt * 5 + l] = (float)mae;
        }
        float sct = (float)(term_corr * sc);
        ssc[tt] = sct;
        out[1 + tt]  = sct;
        out[21 + tt] = (float)r;
    }
    __syncthreads();

    if (threadIdx.x < 5) {
        int l = threadIdx.x;
        float ts = 0.0f, ma = 0.0f;
#pragma unroll
        for (int tt = 0; tt < T_STEPS; tt++) { ts += sts[tt][l]; ma += sma[tt][l]; }
        out[241 + l] = ts / (float)T_STEPS;
        out[246 + l] = ma / (float)T_STEPS;
    }
    if (threadIdx.x == 5) {
        float tot = 0.0f;
#pragma unroll
        for (int tt = 0; tt < T_STEPS; tt++) tot += ssc[tt] * c_tw[tt];
        out[0] = tot;
    }
    if (threadIdx.x == 0) g_ticket = 0u;   // reset for next graph replay
}

extern "C" void kernel_launch(void* const* d_in, const int* in_sizes, int n_in,
                              void* d_out, int out_size) {
    const float* pred = (const float*)d_in[0];
    const float* targ = (const float*)d_in[1];
    const float* mask = (const float*)d_in[2];
    float* out = (float*)d_out;

    dim3 g1(NPB, T_STEPS);
    k_fused<<<g1, TPB>>>(pred, targ, mask, out);
}

// round 4
// speedup vs baseline: 1.6469x; 1.2198x over previous
#include <cuda_runtime.h>

#define T_STEPS 20
#define HW (480*480)            // 230400 floats per (b,t) slab; 57600 float4
#define HW4 57600
#define RANGE4 (2*HW4)          // 115200 float4 across both batch slabs
#define SLABGAP4 (19*HW4)       // f4 gap: slab b=1 starts 19*HW4 past end of b=0 walk
#define NPB 37                  // 37*20 = 740 = 148 SMs * 5 blocks: exactly one wave
#define TPB 256
#define STRIDE (NPB*TPB)        // 9472
#define NACC 26
// partial layout: 0:cnt 1:S1P 2:S1Q 3:S2P 4:S2Q 5:SPQ   (P=p+1, Q=q+1 raw moments)
//                 6..10:ptot 11..15:ttot 16..20:hits 21..25:maecum (cumulative over t>=thr_l)

__device__ float        g_part[T_STEPS * NPB * NACC];
__device__ unsigned int g_ticket;   // zero-init; self-resets each call

__constant__ float c_tw[T_STEPS] = {
    0.0075f, 0.02f, 0.03f, 0.04f, 0.05f, 0.06f, 0.07f, 0.08f, 0.09f, 0.1f,
    0.09f,   0.08f, 0.07f, 0.06f, 0.05f, 0.04f, 0.03f, 0.02f, 0.0075f, 0.005f};

// thresholds mapped to normalized space: ln(1+thr)/ln(31)
#define C0 0.02775496f
#define C1 0.20184909f
#define C2 0.31992323f
#define C3 0.52177232f
#define C4 0.63984647f

struct Acc {
    float s1p, s1t, s2p, s2t, spt;       // raw moments of P=p+1, Q=q+1 (nz-masked)
    float m0, m1, m2, m3, m4;            // cumulative mae: sum d over tn>=C_l
    int   cnt;
    unsigned ptot, ttot, hits;           // 5 x 6-bit packed one-hot counts
};

__device__ __forceinline__ void accum_one(float pn, float tn, float mk, Acc& a) {
    const float K = 4.954196310386875f;   // log2(31)
    float P, Q;                           // P = expm1(pn*ln31)+1 = 31^pn
    asm("ex2.approx.f32 %0, %1;" : "=f"(P) : "f"(pn * K));
    asm("ex2.approx.f32 %0, %1;" : "=f"(Q) : "f"(tn * K));

    bool m  = (mk > 0.5f);
    bool A0 = m && (pn >= C0), A1 = m && (pn >= C1), A2 = m && (pn >= C2),
         A3 = m && (pn >= C3), A4 = m && (pn >= C4);
    bool B0 = m && (tn >= C0), B1 = m && (tn >= C1), B2 = m && (tn >= C2),
         B3 = m && (tn >= C3), B4 = m && (tn >= C4);

    int cp = (int)A0 + (int)A1 + (int)A2 + (int)A3 + (int)A4;
    int ct = (int)B0 + (int)B1 + (int)B2 + (int)B3 + (int)B4;

    // masked & not double-zero: raw moments of P,Q (shift corrected at the end)
    bool nz = A0 || B0;
    float Pm = nz ? P : 0.0f;
    float Qm = nz ? Q : 0.0f;
    a.cnt += (int)nz;
    a.s1p += Pm;
    a.s1t += Qm;
    a.s2p = fmaf(Pm, P, a.s2p);
    a.s2t = fmaf(Qm, Q, a.s2t);
    a.spt = fmaf(Pm, Q, a.spt);

    // packed one-hot histograms (6-bit fields; <=52 elems/thread: no overflow)
    unsigned ohp = (1u << (6 * cp)) >> 6;   // 0 if cp==0
    unsigned oht = (1u << (6 * ct)) >> 6;
    a.ptot += ohp;
    a.ttot += oht;
    a.hits += (cp == ct) ? ohp : 0u;

    // cumulative mae on B_l predicates (differenced in final reduce)
    float d = fabsf(P - Q);                 // == |p - q|
    a.m0 += B0 ? d : 0.0f;
    a.m1 += B1 ? d : 0.0f;
    a.m2 += B2 ? d : 0.0f;
    a.m3 += B3 ? d : 0.0f;
    a.m4 += B4 ? d : 0.0f;
}

__device__ __forceinline__ void accum4(const float4& pv, const float4& tv,
                                       const float4& mv, Acc& a) {
    accum_one(pv.x, tv.x, mv.x, a);
    accum_one(pv.y, tv.y, mv.y, a);
    accum_one(pv.z, tv.z, mv.z, a);
    accum_one(pv.w, tv.w, mv.w, a);
}

__global__ __launch_bounds__(TPB, 5) void k_fused(const float* __restrict__ pred,
                                                  const float* __restrict__ targ,
                                                  const float* __restrict__ mask,
                                                  float* __restrict__ out) {
    const int t   = blockIdx.y;
    const int gid = blockIdx.x * TPB + threadIdx.x;   // 0..9471

    Acc a;
    a.s1p = a.s1t = a.s2p = a.s2t = a.spt = 0.0f;
    a.m0 = a.m1 = a.m2 = a.m3 = a.m4 = 0.0f;
    a.cnt = 0; a.ptot = a.ttot = a.hits = 0u;

    const size_t base4 = (size_t)t * HW4;
    const float4* p4 = (const float4*)pred + base4;
    const float4* t4 = (const float4*)targ + base4;
    const float4* m4 = (const float4*)mask + base4;

    // merged walk across both batch slabs with one-deep software prefetch
    int v = gid;
    int idx = v + ((v >= HW4) ? SLABGAP4 : 0);
    float4 pv = __ldcs(p4 + idx);
    float4 tv = __ldcs(t4 + idx);
    float4 mv = __ldcs(m4 + idx);
#pragma unroll 1
    for (v = gid + STRIDE; v < RANGE4; v += STRIDE) {
        int idx2 = v + ((v >= HW4) ? SLABGAP4 : 0);
        float4 pv2 = __ldcs(p4 + idx2);
        float4 tv2 = __ldcs(t4 + idx2);
        float4 mv2 = __ldcs(m4 + idx2);
        accum4(pv, tv, mv, a);
        pv = pv2; tv = tv2; mv = mv2;
    }
    accum4(pv, tv, mv, a);

    // unpack to 26 floats
    float acc[NACC];
    acc[0] = (float)a.cnt;
    acc[1] = a.s1p; acc[2] = a.s1t; acc[3] = a.s2p; acc[4] = a.s2t; acc[5] = a.spt;
#pragma unroll
    for (int l = 0; l < 5; l++) {
        acc[6  + l] = (float)((a.ptot >> (6 * l)) & 63u);
        acc[11 + l] = (float)((a.ttot >> (6 * l)) & 63u);
        acc[16 + l] = (float)((a.hits >> (6 * l)) & 63u);
    }
    acc[21] = a.m0; acc[22] = a.m1; acc[23] = a.m2; acc[24] = a.m3; acc[25] = a.m4;

    // warp tree reduce (deterministic)
#pragma unroll
    for (int i = 0; i < NACC; i++) {
#pragma unroll
        for (int o = 16; o > 0; o >>= 1)
            acc[i] += __shfl_xor_sync(0xffffffffu, acc[i], o);
    }

    __shared__ float s[TPB / 32][NACC];
    int w = threadIdx.x >> 5, ln = threadIdx.x & 31;
    if (ln == 0) {
#pragma unroll
        for (int i = 0; i < NACC; i++) s[w][i] = acc[i];
    }
    __syncthreads();
    if (threadIdx.x < NACC) {
        float vv = 0.0f;
#pragma unroll
        for (int w2 = 0; w2 < TPB / 32; w2++) vv += s[w2][threadIdx.x];
        g_part[((size_t)t * NPB + blockIdx.x) * NACC + threadIdx.x] = vv;
    }

    // ---- last-block-does-the-rest (deterministic: reads fixed g_part) ----
    __threadfence();
    __syncthreads();
    __shared__ bool amLast;
    if (threadIdx.x == 0) {
        unsigned done = atomicAdd(&g_ticket, 1u);
        amLast = (done == (unsigned)(NPB * T_STEPS - 1));
    }
    __syncthreads();
    if (!amLast) return;
    __threadfence();

    __shared__ double sd[T_STEPS][NACC];
    for (int idx2 = threadIdx.x; idx2 < T_STEPS * NACC; idx2 += TPB) {
        int tt = idx2 / NACC, j = idx2 % NACC;
        double vv = 0.0;
#pragma unroll 8
        for (int k = 0; k < NPB; k++)
            vv += (double)g_part[((size_t)tt * NPB + k) * NACC + j];
        sd[tt][j] = vv;
    }
    __syncthreads();

    __shared__ float sts[T_STEPS][5], sma[T_STEPS][5], ssc[T_STEPS];
    if (threadIdx.x < T_STEPS) {
        int tt = threadIdx.x;
        double C  = sd[tt][0];
        double S1P = sd[tt][1], S1Q = sd[tt][2];
        double S2P = sd[tt][3], S2Q = sd[tt][4], SPQ = sd[tt][5];
        // shift correction: p = P-1, q = Q-1 over nz-masked set of size C
        double S1p = S1P - C, S1t = S1Q - C;
        double S2p = S2P - 2.0 * S1P + C;
        double S2t = S2Q - 2.0 * S1Q + C;
        double Spt = SPQ - S1P - S1Q + C;
        double r = 0.0;
        if (C > 0.0) {
            double num  = Spt - S1p * S1t / C;
            double varp = S2p - S1p * S1p / C;
            double vart = S2t - S1t * S1t / C;
            if (varp < 0.0) varp = 0.0;
            if (vart < 0.0) vart = 0.0;
            r = num / (sqrt(varp * vart) + 1e-6);
            r = fmin(1.0, fmax(-1.0, r));
        }
        double term_corr = sqrt(exp(r - 1.0));
        const double lw[5] = {0.1, 0.1, 0.2, 0.25, 0.35};
        double sc = 0.0;
#pragma unroll
        for (int l = 0; l < 5; l++) {
            double ptot = sd[tt][6 + l], ttot = sd[tt][11 + l];
            double hits = sd[tt][16 + l];
            double maen = sd[tt][21 + l] - ((l < 4) ? sd[tt][22 + l] : 0.0);
            double ts  = hits / (ptot + ttot - hits + 1e-8);
            double mae = (ttot > 0.0) ? (maen / fmax(ttot, 1.0)) : 0.0;
            sc += lw[l] * ts * sqrt(exp(-mae / 100.0));
            sts[tt][l] = (float)ts;
            sma[tt][l] = (float)mae;
            out[41  + tt * 5 + l] = (float)ts;
            out[141 + tt * 5 + l] = (float)mae;
        }
        float sct = (float)(term_corr * sc);
        ssc[tt] = sct;
        out[1 + tt]  = sct;
        out[21 + tt] = (float)r;
    }
    __syncthreads();

    if (threadIdx.x < 5) {
        int l = threadIdx.x;
        float ts = 0.0f, ma = 0.0f;
#pragma unroll
        for (int tt = 0; tt < T_STEPS; tt++) { ts += sts[tt][l]; ma += sma[tt][l]; }
        out[241 + l] = ts / (float)T_STEPS;
        out[246 + l] = ma / (float)T_STEPS;
    }
    if (threadIdx.x == 5) {
        float tot = 0.0f;
#pragma unroll
        for (int tt = 0; tt < T_STEPS; tt++) tot += ssc[tt] * c_tw[tt];
        out[0] = tot;
    }
    if (threadIdx.x == 0) g_ticket = 0u;   // reset for next graph replay
}

extern "C" void kernel_launch(void* const* d_in, const int* in_sizes, int n_in,
                              void* d_out, int out_size) {
    const float* pred = (const float*)d_in[0];
    const float* targ = (const float*)d_in[1];
    const float* mask = (const float*)d_in[2];
    float* out = (float*)d_out;

    dim3 g1(NPB, T_STEPS);
    k_fused<<<g1, TPB>>>(pred, targ, mask, out);
}